// round 5
// baseline (speedup 1.0000x reference)
#include <cuda_runtime.h>
#include <cstdint>
#include <math.h>

typedef unsigned long long u64;

// ---------------------------------------------------------------------------
// Packed f32x2 helpers (Blackwell sm_103a)
// ---------------------------------------------------------------------------
__device__ __forceinline__ u64 ffma2(u64 a, u64 b, u64 c) {
    u64 d;
    asm("fma.rn.f32x2 %0, %1, %2, %3;" : "=l"(d) : "l"(a), "l"(b), "l"(c));
    return d;
}
__device__ __forceinline__ u64 pack2(float x, float y) {
    u64 r;
    asm("mov.b64 %0, {%1, %2};" : "=l"(r) : "f"(x), "f"(y));
    return r;
}
__device__ __forceinline__ float2 unpack2(u64 v) {
    float2 f;
    asm("mov.b64 {%0, %1}, %2;" : "=f"(f.x), "=f"(f.y) : "l"(v));
    return f;
}

// Accurate tanh via ex2.approx (rel err ~2^-22); tanhf under fast-math lowers
// to tanh.approx (abs err ~2^-11) and fails 1e-3 over 1024 recurrent steps.
__device__ __forceinline__ float tanh_acc(float x) {
    float e = __expf(2.0f * x);
    return 1.0f - 2.0f / (e + 1.0f);
}

// ---------------------------------------------------------------------------
// Phase 1: x_proj GEMM (unchanged; ~231us)
// ---------------------------------------------------------------------------
__global__ void __launch_bounds__(256) xproj_kernel(
    const float* __restrict__ X, const float* __restrict__ Wih,
    const float* __restrict__ bih, float* __restrict__ C)
{
    __shared__ __align__(16) float As[16][128];
    __shared__ __align__(16) float Bs[16][128];

    const int tid = threadIdx.x;
    const int tx  = tid & 15;
    const int ty  = tid >> 4;
    const int m0  = blockIdx.y * 128;
    const int n0  = blockIdx.x * 128;

    u64 acc[8][4];
#pragma unroll
    for (int m = 0; m < 8; m++)
#pragma unroll
        for (int n = 0; n < 4; n++) acc[m][n] = 0ull;

    for (int k0 = 0; k0 < 256; k0 += 16) {
#pragma unroll
        for (int i = 0; i < 2; i++) {
            int idx = tid + i * 256;
            int row = idx >> 2;
            int kq  = (idx & 3) << 2;
            float4 xa = *(const float4*)(X + (size_t)(m0 + row) * 256 + k0 + kq);
            As[kq + 0][row] = xa.x; As[kq + 1][row] = xa.y;
            As[kq + 2][row] = xa.z; As[kq + 3][row] = xa.w;
            float4 wa = *(const float4*)(Wih + (size_t)(n0 + row) * 256 + k0 + kq);
            Bs[kq + 0][row] = wa.x; Bs[kq + 1][row] = wa.y;
            Bs[kq + 2][row] = wa.z; Bs[kq + 3][row] = wa.w;
        }
        __syncthreads();

#pragma unroll
        for (int kk = 0; kk < 16; kk++) {
            float4 a0 = *(const float4*)&As[kk][ty * 8];
            float4 a1 = *(const float4*)&As[kk][ty * 8 + 4];
            float4 b0 = *(const float4*)&Bs[kk][tx * 8];
            float4 b1 = *(const float4*)&Bs[kk][tx * 8 + 4];
            u64 bb[4] = { pack2(b0.x, b0.y), pack2(b0.z, b0.w),
                          pack2(b1.x, b1.y), pack2(b1.z, b1.w) };
            float am[8] = { a0.x, a0.y, a0.z, a0.w, a1.x, a1.y, a1.z, a1.w };
#pragma unroll
            for (int m = 0; m < 8; m++) {
                u64 ad = pack2(am[m], am[m]);
#pragma unroll
                for (int n = 0; n < 4; n++) acc[m][n] = ffma2(ad, bb[n], acc[m][n]);
            }
        }
        __syncthreads();
    }

    const int nc = n0 + tx * 8;
    float4 bv0 = *(const float4*)(bih + nc);
    float4 bv1 = *(const float4*)(bih + nc + 4);
#pragma unroll
    for (int m = 0; m < 8; m++) {
        float2 r0 = unpack2(acc[m][0]), r1 = unpack2(acc[m][1]);
        float2 r2 = unpack2(acc[m][2]), r3 = unpack2(acc[m][3]);
        float* cp = C + (size_t)(m0 + ty * 8 + m) * 256 + nc;
        *(float4*)cp       = make_float4(r0.x + bv0.x, r0.y + bv0.y,
                                         r1.x + bv0.z, r1.y + bv0.w);
        *(float4*)(cp + 4) = make_float4(r2.x + bv1.x, r2.y + bv1.y,
                                         r3.x + bv1.z, r3.y + bv1.w);
    }
}

// ---------------------------------------------------------------------------
// Phase 2 (v5): SINGLE-CTA scan, hybrid register/smem weight residency.
//
// One CTA of 256 threads per batch row (grid=64, one SM each, no cluster).
// Thread j owns output j and holds W_hh[j][0:192] in 96 packed f32x2
// registers (48K regs CTA-wide). The tail W_hh[:][192:256] lives in smem,
// pre-paired as u64 (W[j][k],W[j][k+1]) in Wp_sm[kp][j] (64KB), so LDS.64
// feeds ffma2 directly (2-way bank phases, hidden under FMA issue).
//
// Per step: full 256-MAC dot per thread (96 reg-ffma2 + 32 smem-ffma2),
// + xp + b, tanh, store h into the other parity buffer, ONE __syncthreads.
// No cross-CTA traffic of any kind. Step = FMA-issue bound (~512cyc/SMSP).
// ---------------------------------------------------------------------------
__global__ void __launch_bounds__(256, 1)
rnn_scan_kernel(const float* __restrict__ Whh, const float* __restrict__ bhh,
                float* __restrict__ out)
{
    __shared__ __align__(16) u64   Wp_sm[32][256];   // W pairs, k=192..255: 64KB
    __shared__ __align__(16) float h_sm[2][256];     // hidden state, parity buffered

    const int tid = threadIdx.x;                     // = output index j
    const int batch = blockIdx.x;

    // --- W_hh[j][0:192] -> 96 packed f32x2 registers ---
    u64 w2[96];
    {
        const ulonglong2* wrow = (const ulonglong2*)(Whh + (size_t)tid * 256);
#pragma unroll
        for (int i = 0; i < 48; i++) {
            ulonglong2 v = wrow[i];
            w2[2 * i] = v.x; w2[2 * i + 1] = v.y;
        }
    }

    // --- W_hh[:][192:256] -> smem pairs Wp_sm[kp][j], coalesced gmem reads ---
    for (int idx = tid; idx < 32 * 256; idx += 256) {
        int j  = idx >> 5;         // consecutive threads -> consecutive kp: coalesced
        int kp = idx & 31;
        Wp_sm[kp][j] = *(const u64*)(Whh + (size_t)j * 256 + 192 + 2 * kp);
    }

    h_sm[0][tid] = 0.0f;
    h_sm[1][tid] = 0.0f;
    __syncthreads();

    float* outb = out + (size_t)batch * (1024 * 256) + tid;   // column j
    const float bh = bhh[tid];
    float xp_next = outb[0];

    for (int t = 0; t < 1024; t++) {
        const int p = t & 1;
        const ulonglong2* h4 = (const ulonglong2*)&h_sm[p][0];   // broadcast reads

        u64 acc0 = 0ull, acc1 = 0ull, acc2 = 0ull, acc3 = 0ull;

        // k = 0..191 from registers (96 ffma2)
#pragma unroll
        for (int i = 0; i < 48; i++) {
            ulonglong2 hv = h4[i];
            acc0 = ffma2(w2[2 * i],     hv.x, acc0);
            acc1 = ffma2(w2[2 * i + 1], hv.y, acc1);
        }
        // k = 192..255 from smem pairs (32 LDS.64 + 32 ffma2)
#pragma unroll
        for (int i = 0; i < 16; i++) {
            ulonglong2 hv = h4[48 + i];
            acc2 = ffma2(Wp_sm[2 * i][tid],     hv.x, acc2);
            acc3 = ffma2(Wp_sm[2 * i + 1][tid], hv.y, acc3);
        }

        float2 a0 = unpack2(acc0), a1 = unpack2(acc1);
        float2 a2 = unpack2(acc2), a3 = unpack2(acc3);
        const float s = ((a0.x + a0.y) + (a1.x + a1.y))
                      + ((a2.x + a2.y) + (a3.x + a3.y));

        const float h = tanh_acc(s + xp_next + bh);
        if (t < 1023) xp_next = __ldg(outb + (size_t)(t + 1) * 256);

        h_sm[p ^ 1][tid] = h;          // next step's state (other parity: no WAR)
        outb[(size_t)t * 256] = h;     // final output

        __syncthreads();               // h_{t+1} fully written before next reads
    }
}

// ---------------------------------------------------------------------------
// Harness entry. Inputs: x, W_ih, W_hh, b_ih, b_hh. Output fp32 [B,T,H].
// x_proj is materialized into d_out, then overwritten in place by h_t.
// ---------------------------------------------------------------------------
extern "C" void kernel_launch(void* const* d_in, const int* in_sizes, int n_in,
                              void* d_out, int out_size)
{
    const float* x   = (const float*)d_in[0];
    const float* Wih = (const float*)d_in[1];
    const float* Whh = (const float*)d_in[2];
    const float* bih = (const float*)d_in[3];
    const float* bhh = (const float*)d_in[4];
    float* out = (float*)d_out;

    dim3 g1(2, 512);
    xproj_kernel<<<g1, 256>>>(x, Wih, bih, out);

    rnn_scan_kernel<<<64, 256>>>(Whh, bhh, out);
}